// round 3
// baseline (speedup 1.0000x reference)
#include <cuda_runtime.h>
#include <cuda_bf16.h>
#include <cstdint>

#define N_NODES 100000
#define F1 128
#define F2 64

// Scratch buffers (device globals: allocation-free, graph-safe)
__device__ float g_bufA[N_NODES * F2];   // GEMM output (pre-scatter messages)
__device__ float g_bufB[N_NODES * F2];   // scatter accumulation target
__device__ float g_bufC[N_NODES * F2];   // hidden activations h1
__device__ float g_rso[N_NODES];         // rsqrt(deg_out)
__device__ float g_rsi[N_NODES];         // rsqrt(deg_in)
__device__ float g_dego[N_NODES];
__device__ float g_degi[N_NODES];

// ---------------------------------------------------------------------------
// Zero scatter buffer + degree counters (runs once per graph replay)
__global__ void k_zero() {
    int idx = blockIdx.x * blockDim.x + threadIdx.x;
    if (idx < N_NODES * F2) g_bufB[idx] = 0.0f;
    if (idx < N_NODES) { g_dego[idx] = 0.0f; g_degi[idx] = 0.0f; }
}

// ---------------------------------------------------------------------------
// Degree accumulation
__global__ void k_degree(const int* __restrict__ src, const int* __restrict__ dst, int E) {
    int i = blockIdx.x * blockDim.x + threadIdx.x;
    if (i >= E) return;
    atomicAdd(&g_dego[src[i]], 1.0f);
    atomicAdd(&g_degi[dst[i]], 1.0f);
}

__global__ void k_rsqrt() {
    int i = blockIdx.x * blockDim.x + threadIdx.x;
    if (i >= N_NODES) return;
    g_rso[i] = rsqrtf(fmaxf(g_dego[i], 1.0f));
    g_rsi[i] = rsqrtf(fmaxf(g_degi[i], 1.0f));
}

// ---------------------------------------------------------------------------
// Y[r, :] = (X[r, :] @ W) * g_rso[r]     X:[M,K]  W:[K,64]  Y:[M,64]
// 64-row tile per block, 256 threads, 4x4 register blocking, W fully in smem.
template <int K>
__global__ void k_gemm_scale(const float* __restrict__ X, const float* __restrict__ W,
                             float* __restrict__ Y, int M) {
    extern __shared__ float smem[];
    float* sW = smem;            // [K][64]
    float* sX = smem + K * 64;   // [64][K]

    const int tid = threadIdx.x;
    const int row0 = blockIdx.x * 64;

    // Load W (whole matrix)
    for (int i = tid; i < K * 64 / 4; i += 256)
        ((float4*)sW)[i] = ((const float4*)W)[i];

    // Load X tile (zero-fill out-of-range rows)
    const int RV = K / 4;  // float4 per row
    for (int i = tid; i < 64 * RV; i += 256) {
        int r = i / RV, c = i % RV;
        float4 v = make_float4(0.f, 0.f, 0.f, 0.f);
        if (row0 + r < M)
            v = ((const float4*)(X + (size_t)(row0 + r) * K))[c];
        ((float4*)sX)[i] = v;
    }
    __syncthreads();

    const int tx = tid & 15;   // output-col group (4 cols)
    const int ty = tid >> 4;   // row group (4 rows)

    float acc[4][4];
#pragma unroll
    for (int j = 0; j < 4; j++)
#pragma unroll
        for (int c = 0; c < 4; c++) acc[j][c] = 0.0f;

    for (int k4 = 0; k4 < K / 4; ++k4) {
        float4 xv[4];
#pragma unroll
        for (int j = 0; j < 4; j++)
            xv[j] = ((const float4*)(sX + (ty * 4 + j) * K))[k4];
#pragma unroll
        for (int kk = 0; kk < 4; kk++) {
            float4 wv = ((const float4*)(sW + (k4 * 4 + kk) * 64))[tx];
#pragma unroll
            for (int j = 0; j < 4; j++) {
                const float* xp = (const float*)&xv[j];
                float xs = xp[kk];
                acc[j][0] += xs * wv.x;
                acc[j][1] += xs * wv.y;
                acc[j][2] += xs * wv.z;
                acc[j][3] += xs * wv.w;
            }
        }
    }

#pragma unroll
    for (int j = 0; j < 4; j++) {
        int gr = row0 + ty * 4 + j;
        if (gr < M) {
            float s = g_rso[gr];
            float4 o = make_float4(acc[j][0] * s, acc[j][1] * s, acc[j][2] * s, acc[j][3] * s);
            ((float4*)(Y + (size_t)gr * 64))[tx] = o;
        }
    }
}

// ---------------------------------------------------------------------------
// g_bufB[dst[e], :] += g_bufA[src[e], :]  — 16 threads per edge, float4 lanes,
// vector reduction (red.global.add.v4.f32, sm_90+), no return value.
__global__ void k_scatter(const int* __restrict__ src, const int* __restrict__ dst, int E) {
    int idx = blockIdx.x * blockDim.x + threadIdx.x;
    if (idx >= E * 16) return;
    int e = idx >> 4;
    int c = idx & 15;
    int s = __ldg(src + e);
    int d = __ldg(dst + e);
    float4 v = __ldg(((const float4*)g_bufA) + (size_t)s * 16 + c);
    float* p = g_bufB + (size_t)d * 64 + c * 4;
    asm volatile("red.global.add.v4.f32 [%0], {%1, %2, %3, %4};"
                 :: "l"(p), "f"(v.x), "f"(v.y), "f"(v.z), "f"(v.w)
                 : "memory");
}

// ---------------------------------------------------------------------------
// h1 = relu(B * rsqrt(deg_in) + b1); also re-zeros B for the second scatter.
__global__ void k_epilogue1(const float* __restrict__ b1) {
    int idx = blockIdx.x * blockDim.x + threadIdx.x;
    if (idx >= N_NODES * 16) return;
    int node = idx >> 4;
    int c = idx & 15;
    float s = g_rsi[node];
    float4 v = ((float4*)g_bufB)[idx];
    float4 bb = __ldg(((const float4*)b1) + c);
    v.x = fmaxf(v.x * s + bb.x, 0.0f);
    v.y = fmaxf(v.y * s + bb.y, 0.0f);
    v.z = fmaxf(v.z * s + bb.z, 0.0f);
    v.w = fmaxf(v.w * s + bb.w, 0.0f);
    ((float4*)g_bufC)[idx] = v;
    ((float4*)g_bufB)[idx] = make_float4(0.f, 0.f, 0.f, 0.f);
}

// out = B * rsqrt(deg_in) + b2
__global__ void k_epilogue2(const float* __restrict__ b2, float* __restrict__ out) {
    int idx = blockIdx.x * blockDim.x + threadIdx.x;
    if (idx >= N_NODES * 16) return;
    int node = idx >> 4;
    int c = idx & 15;
    float s = g_rsi[node];
    float4 v = ((float4*)g_bufB)[idx];
    float4 bb = __ldg(((const float4*)b2) + c);
    v.x = v.x * s + bb.x;
    v.y = v.y * s + bb.y;
    v.z = v.z * s + bb.z;
    v.w = v.w * s + bb.w;
    ((float4*)out)[idx] = v;
}

// ---------------------------------------------------------------------------
extern "C" void kernel_launch(void* const* d_in, const int* in_sizes, int n_in,
                              void* d_out, int out_size) {
    const float* x   = (const float*)d_in[0];
    const int*   src = (const int*)  d_in[1];
    const int*   dst = (const int*)  d_in[2];
    const float* W1  = (const float*)d_in[3];
    const float* b1  = (const float*)d_in[4];
    const float* W2  = (const float*)d_in[5];
    const float* b2  = (const float*)d_in[6];
    float* out = (float*)d_out;

    const int E = in_sizes[1];
    const int M = in_sizes[0] / F1;  // == N_NODES

    void* pA = nullptr; void* pC = nullptr;
    cudaGetSymbolAddress(&pA, g_bufA);
    cudaGetSymbolAddress(&pC, g_bufC);

    const int T = 256;
    const int smem1 = (F1 * 64 + 64 * F1) * 4;  // 64 KB
    const int smem2 = (F2 * 64 + 64 * F2) * 4;  // 32 KB
    cudaFuncSetAttribute(k_gemm_scale<F1>, cudaFuncAttributeMaxDynamicSharedMemorySize, smem1);
    cudaFuncSetAttribute(k_gemm_scale<F2>, cudaFuncAttributeMaxDynamicSharedMemorySize, smem2);

    // 1) zero scatter target + degree counters
    k_zero<<<(N_NODES * F2 + T - 1) / T, T>>>();
    // 2) degrees
    k_degree<<<(E + T - 1) / T, T>>>(src, dst, E);
    // 3) rsqrt norms
    k_rsqrt<<<(N_NODES + T - 1) / T, T>>>();
    // 4) layer 1 GEMM first (64-wide messages instead of 128): A = (x @ W1) * rso
    k_gemm_scale<F1><<<(M + 63) / 64, 256, smem1>>>(x, W1, (float*)pA, M);
    // 5) scatter-sum over edges: B[dst] += A[src]
    k_scatter<<<(E * 16 + T - 1) / T, T>>>(src, dst, E);
    // 6) h1 = relu(B * rsi + b1); rezero B
    k_epilogue1<<<(N_NODES * 16 + T - 1) / T, T>>>(b1);
    // 7) layer 2 GEMM: A = (h1 @ W2) * rso
    k_gemm_scale<F2><<<(M + 63) / 64, 256, smem2>>>((const float*)pC, W2, (float*)pA, M);
    // 8) scatter-sum layer 2
    k_scatter<<<(E * 16 + T - 1) / T, T>>>(src, dst, E);
    // 9) out = B * rsi + b2
    k_epilogue2<<<(N_NODES * 16 + T - 1) / T, T>>>(b2, out);
}

// round 4
// speedup vs baseline: 2.2293x; 2.2293x over previous
#include <cuda_runtime.h>
#include <cuda_bf16.h>
#include <cstdint>

#define N_NODES 100000
#define F1 128
#define F2 64
#define EMAX 1600000

// Scratch (device globals: allocation-free, graph-safe)
__device__ float g_bufA[N_NODES * F2];   // GEMM output (pre-aggregation messages)
__device__ float g_bufC[N_NODES * F2];   // hidden activations h1
__device__ float g_rso[N_NODES];         // rsqrt(deg_out)
__device__ float g_rsi[N_NODES];         // rsqrt(deg_in)
__device__ int   g_dego[N_NODES];
__device__ int   g_degi[N_NODES];
__device__ int   g_off[N_NODES];         // segment start per dst node
__device__ int   g_cur[N_NODES];         // fill cursor per dst node
__device__ int   g_sorted[EMAX];         // src indices grouped by dst
__device__ int   g_total;                // segment allocator

// ---------------------------------------------------------------------------
__global__ void k_zero() {
    int i = blockIdx.x * blockDim.x + threadIdx.x;
    if (i < N_NODES) { g_dego[i] = 0; g_degi[i] = 0; }
    if (i == 0) g_total = 0;
}

__global__ void k_degree(const int* __restrict__ src, const int* __restrict__ dst, int E) {
    int i = blockIdx.x * blockDim.x + threadIdx.x;
    if (i >= E) return;
    atomicAdd(&g_dego[src[i]], 1);
    atomicAdd(&g_degi[dst[i]], 1);
}

// Allocate a contiguous segment per dst node (warp scan + 1 atomic/warp),
// fused with norm computation.
__global__ void k_alloc() {
    int i = blockIdx.x * blockDim.x + threadIdx.x;
    int lane = threadIdx.x & 31;
    int deg = 0, dego = 0;
    if (i < N_NODES) { deg = g_degi[i]; dego = g_dego[i]; }
    // warp inclusive scan of deg
    int incl = deg;
#pragma unroll
    for (int o = 1; o < 32; o <<= 1) {
        int n = __shfl_up_sync(0xFFFFFFFFu, incl, o);
        if (lane >= o) incl += n;
    }
    int wtotal = __shfl_sync(0xFFFFFFFFu, incl, 31);
    int base = 0;
    if (lane == 0) base = atomicAdd(&g_total, wtotal);
    base = __shfl_sync(0xFFFFFFFFu, base, 0);
    if (i < N_NODES) {
        int off = base + incl - deg;
        g_off[i] = off;
        g_cur[i] = off;
        g_rsi[i] = rsqrtf((float)max(deg, 1));
        g_rso[i] = rsqrtf((float)max(dego, 1));
    }
}

// Group src indices by dst
__global__ void k_bin(const int* __restrict__ src, const int* __restrict__ dst, int E) {
    int e = blockIdx.x * blockDim.x + threadIdx.x;
    if (e >= E) return;
    int d = dst[e];
    int p = atomicAdd(&g_cur[d], 1);
    g_sorted[p] = src[e];
}

// ---------------------------------------------------------------------------
// Y[r, :] = (X[r, :] @ W) * g_rso[r]   (unchanged from R1 — known correct)
template <int K>
__global__ void k_gemm_scale(const float* __restrict__ X, const float* __restrict__ W,
                             float* __restrict__ Y, int M) {
    extern __shared__ float smem[];
    float* sW = smem;            // [K][64]
    float* sX = smem + K * 64;   // [64][K]

    const int tid = threadIdx.x;
    const int row0 = blockIdx.x * 64;

    for (int i = tid; i < K * 64 / 4; i += 256)
        ((float4*)sW)[i] = ((const float4*)W)[i];

    const int RV = K / 4;
    for (int i = tid; i < 64 * RV; i += 256) {
        int r = i / RV, c = i % RV;
        float4 v = make_float4(0.f, 0.f, 0.f, 0.f);
        if (row0 + r < M)
            v = ((const float4*)(X + (size_t)(row0 + r) * K))[c];
        ((float4*)sX)[i] = v;
    }
    __syncthreads();

    const int tx = tid & 15;
    const int ty = tid >> 4;

    float acc[4][4];
#pragma unroll
    for (int j = 0; j < 4; j++)
#pragma unroll
        for (int c = 0; c < 4; c++) acc[j][c] = 0.0f;

    for (int k4 = 0; k4 < K / 4; ++k4) {
        float4 xv[4];
#pragma unroll
        for (int j = 0; j < 4; j++)
            xv[j] = ((const float4*)(sX + (ty * 4 + j) * K))[k4];
#pragma unroll
        for (int kk = 0; kk < 4; kk++) {
            float4 wv = ((const float4*)(sW + (k4 * 4 + kk) * 64))[tx];
#pragma unroll
            for (int j = 0; j < 4; j++) {
                const float* xp = (const float*)&xv[j];
                float xs = xp[kk];
                acc[j][0] += xs * wv.x;
                acc[j][1] += xs * wv.y;
                acc[j][2] += xs * wv.z;
                acc[j][3] += xs * wv.w;
            }
        }
    }

#pragma unroll
    for (int j = 0; j < 4; j++) {
        int gr = row0 + ty * 4 + j;
        if (gr < M) {
            float s = g_rso[gr];
            float4 o = make_float4(acc[j][0] * s, acc[j][1] * s, acc[j][2] * s, acc[j][3] * s);
            ((float4*)(Y + (size_t)gr * 64))[tx] = o;
        }
    }
}

// ---------------------------------------------------------------------------
// Gather-aggregate per dst node (no atomics), fused epilogue:
//   out[n] = act( rsi[n] * sum_{s in seg(n)} A[s] + bias )
// 16 threads per node; lanes of a half-warp read the same index (broadcast)
// and consecutive float4s of the source row (coalesced).
template <bool RELU>
__global__ void k_agg(const float* __restrict__ Asrc, const float* __restrict__ bias,
                      float* __restrict__ out) {
    int idx = blockIdx.x * blockDim.x + threadIdx.x;
    if (idx >= N_NODES * 16) return;
    int node = idx >> 4;
    int c = idx & 15;

    int base = g_off[node];
    int deg  = g_degi[node];
    int end  = base + deg;

    const float4* A = (const float4*)Asrc;
    float4 acc = make_float4(0.f, 0.f, 0.f, 0.f);

    int i = base;
    for (; i + 4 <= end; i += 4) {
        int s0 = __ldg(g_sorted + i);
        int s1 = __ldg(g_sorted + i + 1);
        int s2 = __ldg(g_sorted + i + 2);
        int s3 = __ldg(g_sorted + i + 3);
        float4 v0 = __ldg(A + (size_t)s0 * 16 + c);
        float4 v1 = __ldg(A + (size_t)s1 * 16 + c);
        float4 v2 = __ldg(A + (size_t)s2 * 16 + c);
        float4 v3 = __ldg(A + (size_t)s3 * 16 + c);
        acc.x += (v0.x + v1.x) + (v2.x + v3.x);
        acc.y += (v0.y + v1.y) + (v2.y + v3.y);
        acc.z += (v0.z + v1.z) + (v2.z + v3.z);
        acc.w += (v0.w + v1.w) + (v2.w + v3.w);
    }
    for (; i < end; ++i) {
        int s = __ldg(g_sorted + i);
        float4 v = __ldg(A + (size_t)s * 16 + c);
        acc.x += v.x; acc.y += v.y; acc.z += v.z; acc.w += v.w;
    }

    float sc = g_rsi[node];
    float4 bb = __ldg(((const float4*)bias) + c);
    float4 o;
    o.x = acc.x * sc + bb.x;
    o.y = acc.y * sc + bb.y;
    o.z = acc.z * sc + bb.z;
    o.w = acc.w * sc + bb.w;
    if (RELU) {
        o.x = fmaxf(o.x, 0.f); o.y = fmaxf(o.y, 0.f);
        o.z = fmaxf(o.z, 0.f); o.w = fmaxf(o.w, 0.f);
    }
    ((float4*)out)[idx] = o;
}

// ---------------------------------------------------------------------------
extern "C" void kernel_launch(void* const* d_in, const int* in_sizes, int n_in,
                              void* d_out, int out_size) {
    const float* x   = (const float*)d_in[0];
    const int*   src = (const int*)  d_in[1];
    const int*   dst = (const int*)  d_in[2];
    const float* W1  = (const float*)d_in[3];
    const float* b1  = (const float*)d_in[4];
    const float* W2  = (const float*)d_in[5];
    const float* b2  = (const float*)d_in[6];
    float* out = (float*)d_out;

    const int E = in_sizes[1];
    const int M = in_sizes[0] / F1;  // == N_NODES

    void* pA = nullptr; void* pC = nullptr;
    cudaGetSymbolAddress(&pA, g_bufA);
    cudaGetSymbolAddress(&pC, g_bufC);

    const int T = 256;
    const int smem1 = (F1 * 64 + 64 * F1) * 4;  // 64 KB
    const int smem2 = (F2 * 64 + 64 * F2) * 4;  // 32 KB
    cudaFuncSetAttribute(k_gemm_scale<F1>, cudaFuncAttributeMaxDynamicSharedMemorySize, smem1);
    cudaFuncSetAttribute(k_gemm_scale<F2>, cudaFuncAttributeMaxDynamicSharedMemorySize, smem2);

    // 1) zero int degrees + allocator
    k_zero<<<(N_NODES + T - 1) / T, T>>>();
    // 2) integer degrees
    k_degree<<<(E + T - 1) / T, T>>>(src, dst, E);
    // 3) per-node segment allocation + rsqrt norms (fused)
    k_alloc<<<(N_NODES + T - 1) / T, T>>>();
    // 4) group src indices by dst (counting sort placement)
    k_bin<<<(E + T - 1) / T, T>>>(src, dst, E);
    // 5) layer 1 GEMM first (64-wide messages): A = (x @ W1) * rso
    k_gemm_scale<F1><<<(M + 63) / 64, 256, smem1>>>(x, W1, (float*)pA, M);
    // 6) gather-aggregate + epilogue: h1 = relu(rsi * sum A[srcs] + b1)
    k_agg<true><<<(N_NODES * 16 + T - 1) / T, T>>>((const float*)pA, b1, (float*)pC);
    // 7) layer 2 GEMM: A = (h1 @ W2) * rso
    k_gemm_scale<F2><<<(M + 63) / 64, 256, smem2>>>((const float*)pC, W2, (float*)pA, M);
    // 8) gather-aggregate + epilogue: out = rsi * sum A[srcs] + b2
    k_agg<false><<<(N_NODES * 16 + T - 1) / T, T>>>((const float*)pA, b2, out);
}